// round 12
// baseline (speedup 1.0000x reference)
#include <cuda_runtime.h>
#include <cuda_fp16.h>

#define B_TOTAL   131072
#define T_STEPS   7
#define F_IN      60
#define UNITS     256
#define NCOLS     1024      // 4 * UNITS
#define BM        32        // batch rows per CTA (single 32-row band)
#define SXH       96        // x smem row stride (halves); conflict-free LDS.128 phases
#define SHH       288       // h smem row stride (halves); conflict-free LDS.128 phases
#define SC        260       // c smem row stride (fp32); banks = lane, conflict-free
#define NTHREADS  512       // 16 warps: (wh 0..1 = ch2 half) x (wn 0..7)

// Packed fp16 weights, m16n8k16-fragment-ordered. IDENTICAL layout to the verified round-9 pack.
__device__ uint4 g_Wp[2 * NCOLS * 4];   // 128 KB (K padded 60 -> 64)
__device__ uint4 g_Up[8 * NCOLS * 4];   // 512 KB
__device__ float g_bp[NCOLS];           // bias permuted to logical order

// logical column -> physical column (VERBATIM from round 9 - verified)
__device__ __forceinline__ int phys_col(int Lp) {
    int ch = Lp >> 7;
    int l  = Lp & 127;
    int wn = l >> 4;
    int nt = (l >> 3) & 1;
    int w  = l & 7;
    int gate = nt * 2 + (w & 1);
    int unit = ch * 32 + wn * 4 + (w >> 1);
    return gate * UNITS + unit;
}

// k -> packed position in A smem row (VERBATIM from round 9 - verified)
__device__ __forceinline__ int kpos(int k) {
    return (k & ~31) + ((k & 7) >> 1) * 8 + ((k >> 4) & 1) * 4 + ((k >> 3) & 1) * 2 + (k & 1);
}

__device__ __forceinline__ unsigned h2u(float a, float b) {
    __half2 h = __floats2half2_rn(a, b);
    return *reinterpret_cast<unsigned*>(&h);
}

__global__ void pack_kernel(const float* __restrict__ W,
                            const float* __restrict__ U,
                            const float* __restrict__ b) {
    int idx = blockIdx.x * blockDim.x + threadIdx.x;   // 0 .. 32767
    if (idx < 8 * NCOLS * 4) {
        int q   = idx & 3;
        int Lp  = (idx >> 2) & (NCOLS - 1);
        int ko4 = idx >> 12;
        int p   = phys_col(Lp);
        int k0  = ko4 * 32 + 2 * q;
        g_Up[idx] = make_uint4(
            h2u(U[(k0     ) * NCOLS + p], U[(k0 +  1) * NCOLS + p]),
            h2u(U[(k0 +  8) * NCOLS + p], U[(k0 +  9) * NCOLS + p]),
            h2u(U[(k0 + 16) * NCOLS + p], U[(k0 + 17) * NCOLS + p]),
            h2u(U[(k0 + 24) * NCOLS + p], U[(k0 + 25) * NCOLS + p]));
    }
    if (idx < 2 * NCOLS * 4) {
        int q   = idx & 3;
        int Lp  = (idx >> 2) & (NCOLS - 1);
        int ko4 = idx >> 12;
        int p   = phys_col(Lp);
        int k0  = ko4 * 32 + 2 * q;
        #define WV(kk) (((kk) < F_IN) ? W[(kk) * NCOLS + p] : 0.0f)
        g_Wp[idx] = make_uint4(
            h2u(WV(k0),      WV(k0 +  1)),
            h2u(WV(k0 +  8), WV(k0 +  9)),
            h2u(WV(k0 + 16), WV(k0 + 17)),
            h2u(WV(k0 + 24), WV(k0 + 25)));
        #undef WV
    }
    if (idx < NCOLS) {
        g_bp[idx] = b[phys_col(idx)];
    }
}

__device__ __forceinline__ void mma16(float (&c)[4], const unsigned (&a)[4],
                                      unsigned b0, unsigned b1) {
    asm volatile(
        "mma.sync.aligned.m16n8k16.row.col.f32.f16.f16.f32 "
        "{%0,%1,%2,%3}, {%4,%5,%6,%7}, {%8,%9}, {%0,%1,%2,%3};\n"
        : "+f"(c[0]), "+f"(c[1]), "+f"(c[2]), "+f"(c[3])
        : "r"(a[0]), "r"(a[1]), "r"(a[2]), "r"(a[3]), "r"(b0), "r"(b1));
}

__device__ __forceinline__ float sigmoidf_(float x) {
    return __fdividef(1.0f, 1.0f + __expf(-x));
}
__device__ __forceinline__ float tanhf_(float x) {
    return 1.0f - __fdividef(2.0f, __expf(2.0f * x) + 1.0f);
}

// Round-9 gemm16, with the single change arowBase = rA (wm removed; BM=32 band).
template <int KOT4>
__device__ __forceinline__ void gemm16(
    float (&acc)[2][2][2][4], const __half* __restrict__ As, int aStride,
    const uint4* __restrict__ Bp, int idxBase, int lane)
{
    const int q  = lane & 3;
    const int rA = lane >> 2;

    uint4 bbuf[2][2][2];
    #pragma unroll
    for (int p = 0; p < 2 && p < KOT4; ++p)
        #pragma unroll
        for (int cp = 0; cp < 2; ++cp)
            #pragma unroll
            for (int nt = 0; nt < 2; ++nt)
                bbuf[p][cp][nt] = Bp[idxBase + p * 4096 + cp * 512 + nt * 32];

    #pragma unroll
    for (int ko4 = 0; ko4 < KOT4; ++ko4) {
        const int p = ko4 & 1;

        unsigned a[2][2][4];   // [blk][mt][frag]
        #pragma unroll
        for (int mt = 0; mt < 2; ++mt) {
            const __half* ap = As + (rA + mt * 16) * aStride + ko4 * 32 + q * 8;
            uint4 lo = *reinterpret_cast<const uint4*>(ap);
            uint4 hi = *reinterpret_cast<const uint4*>(ap + 8 * aStride);
            a[0][mt][0] = lo.x; a[0][mt][1] = hi.x; a[0][mt][2] = lo.y; a[0][mt][3] = hi.y;
            a[1][mt][0] = lo.z; a[1][mt][1] = hi.z; a[1][mt][2] = lo.w; a[1][mt][3] = hi.w;
        }

        #pragma unroll
        for (int cp = 0; cp < 2; ++cp) {
            #pragma unroll
            for (int nt = 0; nt < 2; ++nt) {
                uint4 b = bbuf[p][cp][nt];
                mma16(acc[0][cp][nt], a[0][0], b.x, b.y);
                mma16(acc[1][cp][nt], a[0][1], b.x, b.y);
                mma16(acc[0][cp][nt], a[1][0], b.z, b.w);
                mma16(acc[1][cp][nt], a[1][1], b.z, b.w);
            }
        }

        if (ko4 + 2 < KOT4) {
            #pragma unroll
            for (int cp = 0; cp < 2; ++cp)
                #pragma unroll
                for (int nt = 0; nt < 2; ++nt)
                    bbuf[p][cp][nt] = Bp[idxBase + (ko4 + 2) * 4096 + cp * 512 + nt * 32];
        }
    }
}

__global__ void __launch_bounds__(NTHREADS, 1)
lstm_enc_kernel(const float* __restrict__ xg, float* __restrict__ out)
{
    extern __shared__ char smemc[];
    float*  cs = reinterpret_cast<float*>(smemc);                               // [BM][SC]
    __half* xs = reinterpret_cast<__half*>(smemc + BM * SC * 4);                // [BM][SXH]
    __half* hs = reinterpret_cast<__half*>(smemc + BM * SC * 4 + BM * SXH * 2); // [2][BM][SHH]

    const int tid  = threadIdx.x;
    const int lane = tid & 31;
    const int warp = tid >> 5;
    const int wh   = warp >> 3;       // 0..1: which ch2 pair this warp owns
    const int wn   = warp & 7;        // 0..7 (same role as round 9)
    const int q    = lane & 3;
    const int rA   = lane >> 2;
    const int row0 = blockIdx.x * BM;

    for (int idx = tid; idx < BM * SC; idx += NTHREADS) cs[idx] = 0.0f;

    for (int t = 0; t < T_STEPS; ++t) {
        __syncthreads();

        // stage x_t as fp16 packed; zero-pad k=60..63 (round-9 form)
        for (int idx = tid; idx < BM * F_IN; idx += NTHREADS) {
            int row = idx / F_IN;
            int col = idx - row * F_IN;
            float v = xg[(size_t)(row0 + row) * (T_STEPS * F_IN) + t * F_IN + col];
            xs[row * SXH + kpos(col)] = __float2half_rn(v);
        }
        for (int idx = tid; idx < BM * 4; idx += NTHREADS) {
            int row = idx >> 2;
            xs[row * SXH + kpos(60 + (idx & 3))] = __ushort_as_half(0);
        }
        __syncthreads();

        const int rb = t & 1;
        const __half* hrd = hs + rb * (BM * SHH);
        __half*       hwr = hs + (rb ^ 1) * (BM * SHH);

        // each warp runs 2 of the 4 ch2 passes -> every B slice loaded by exactly one warp
        for (int c2 = 0; c2 < 2; ++c2) {
            const int ch2 = wh * 2 + c2;
            const int idxBase = ((ch2 * 256 + wn * 16 + rA) << 2) + q;

            float acc[2][2][2][4];
            const float2* bp2 = reinterpret_cast<const float2*>(g_bp);
            #pragma unroll
            for (int cp = 0; cp < 2; ++cp) {
                const int ch = ch2 * 2 + cp;
                #pragma unroll
                for (int nt = 0; nt < 2; ++nt) {
                    float2 bb = bp2[ch * 64 + wn * 8 + nt * 4 + q];
                    acc[0][cp][nt][0] = bb.x; acc[0][cp][nt][1] = bb.y;
                    acc[0][cp][nt][2] = bb.x; acc[0][cp][nt][3] = bb.y;
                    acc[1][cp][nt][0] = bb.x; acc[1][cp][nt][1] = bb.y;
                    acc[1][cp][nt][2] = bb.x; acc[1][cp][nt][3] = bb.y;
                }
            }

            gemm16<2>(acc, xs, SXH, g_Wp, idxBase, lane);
            if (t > 0)
                gemm16<8>(acc, hrd, SHH, g_Up, idxBase, lane);

            // epilogue (VERBATIM round-9 formulas; rowL without wm)
            #pragma unroll
            for (int cp = 0; cp < 2; ++cp) {
                const int unit = (ch2 * 2 + cp) * 32 + wn * 4 + q;
                const int kp   = kpos(unit);
                #pragma unroll
                for (int mt = 0; mt < 2; ++mt) {
                    const int rowL = mt * 16 + rA;
                    float zi0 = acc[mt][cp][0][0], zf0 = acc[mt][cp][0][1];
                    float zi1 = acc[mt][cp][0][2], zf1 = acc[mt][cp][0][3];
                    float zg0 = acc[mt][cp][1][0], zo0 = acc[mt][cp][1][1];
                    float zg1 = acc[mt][cp][1][2], zo1 = acc[mt][cp][1][3];

                    float c0 = cs[rowL * SC + unit];
                    float c1 = cs[(rowL + 8) * SC + unit];
                    float cn0 = sigmoidf_(zf0) * c0 + sigmoidf_(zi0) * tanhf_(zg0);
                    float cn1 = sigmoidf_(zf1) * c1 + sigmoidf_(zi1) * tanhf_(zg1);
                    cs[rowL * SC + unit]       = cn0;
                    cs[(rowL + 8) * SC + unit] = cn1;
                    float h0 = sigmoidf_(zo0) * tanhf_(cn0);
                    float h1 = sigmoidf_(zo1) * tanhf_(cn1);

                    hwr[rowL * SHH + kp]       = __float2half_rn(h0);
                    hwr[(rowL + 8) * SHH + kp] = __float2half_rn(h1);

                    if (t == T_STEPS - 1) {
                        size_t g0i = (size_t)(row0 + rowL) * UNITS + unit;
                        size_t g1i = (size_t)(row0 + rowL + 8) * UNITS + unit;
                        const size_t HOFF = (size_t)B_TOTAL * UNITS;
                        const size_t COFF = 2 * HOFF;
                        out[g0i] = h0;          out[g1i] = h1;
                        out[HOFF + g0i] = h0;   out[HOFF + g1i] = h1;
                        out[COFF + g0i] = cn0;  out[COFF + g1i] = cn1;
                    }
                }
            }
        }
    }
}

extern "C" void kernel_launch(void* const* d_in, const int* in_sizes, int n_in,
                              void* d_out, int out_size) {
    const float* x = nullptr;
    const float* W = nullptr;
    const float* U = nullptr;
    const float* b = nullptr;
    for (int i = 0; i < n_in; ++i) {
        switch (in_sizes[i]) {
            case B_TOTAL * T_STEPS * F_IN: x = (const float*)d_in[i]; break;
            case F_IN * NCOLS:             W = (const float*)d_in[i]; break;
            case UNITS * NCOLS:            U = (const float*)d_in[i]; break;
            case NCOLS:                    b = (const float*)d_in[i]; break;
            default: break;
        }
    }
    if (!x) x = (const float*)d_in[0];
    if (!W) W = (const float*)d_in[1];
    if (!U) U = (const float*)d_in[2];
    if (!b) b = (const float*)d_in[3];

    float* out = (float*)d_out;

    pack_kernel<<<128, 256>>>(W, U, b);

    // smem: c fp32 [32][260] + x fp16 [32][96] + h fp16 [2][32][288] = 76288 B
    const int smem_bytes = BM * SC * 4 + BM * SXH * 2 + 2 * BM * SHH * 2;
    cudaFuncSetAttribute(lstm_enc_kernel,
                         cudaFuncAttributeMaxDynamicSharedMemorySize, smem_bytes);
    lstm_enc_kernel<<<B_TOTAL / BM, NTHREADS, smem_bytes>>>(x, out);
}

// round 14
// speedup vs baseline: 1.2295x; 1.2295x over previous
#include <cuda_runtime.h>
#include <cuda_fp16.h>

#define B_TOTAL   131072
#define T_STEPS   7
#define F_IN      60
#define UNITS     256
#define NCOLS     1024      // 4 * UNITS
#define BM        32        // batch rows per CTA (single 32-row band)
#define SXH       96        // x smem row stride (halves); conflict-free LDS.128 phases
#define SHH       288       // h smem row stride (halves); conflict-free LDS.128 phases
#define SC        260       // c smem row stride (fp32); banks = lane, conflict-free
#define NTHREADS  256       // 8 warps (wn 0..7); each runs all 4 ch2 passes; 2 CTAs/SM

// Packed fp16 weights, m16n8k16-fragment-ordered. IDENTICAL layout to verified round-9 pack.
__device__ uint4 g_Wp[2 * NCOLS * 4];   // 128 KB (K padded 60 -> 64)
__device__ uint4 g_Up[8 * NCOLS * 4];   // 512 KB
__device__ float g_bp[NCOLS];           // bias permuted to logical order

// logical column -> physical column (VERBATIM - verified)
__device__ __forceinline__ int phys_col(int Lp) {
    int ch = Lp >> 7;
    int l  = Lp & 127;
    int wn = l >> 4;
    int nt = (l >> 3) & 1;
    int w  = l & 7;
    int gate = nt * 2 + (w & 1);
    int unit = ch * 32 + wn * 4 + (w >> 1);
    return gate * UNITS + unit;
}

// k -> packed position in A smem row (VERBATIM - verified)
__device__ __forceinline__ int kpos(int k) {
    return (k & ~31) + ((k & 7) >> 1) * 8 + ((k >> 4) & 1) * 4 + ((k >> 3) & 1) * 2 + (k & 1);
}

__device__ __forceinline__ unsigned h2u(float a, float b) {
    __half2 h = __floats2half2_rn(a, b);
    return *reinterpret_cast<unsigned*>(&h);
}

__global__ void pack_kernel(const float* __restrict__ W,
                            const float* __restrict__ U,
                            const float* __restrict__ b) {
    int idx = blockIdx.x * blockDim.x + threadIdx.x;   // 0 .. 32767
    if (idx < 8 * NCOLS * 4) {
        int q   = idx & 3;
        int Lp  = (idx >> 2) & (NCOLS - 1);
        int ko4 = idx >> 12;
        int p   = phys_col(Lp);
        int k0  = ko4 * 32 + 2 * q;
        g_Up[idx] = make_uint4(
            h2u(U[(k0     ) * NCOLS + p], U[(k0 +  1) * NCOLS + p]),
            h2u(U[(k0 +  8) * NCOLS + p], U[(k0 +  9) * NCOLS + p]),
            h2u(U[(k0 + 16) * NCOLS + p], U[(k0 + 17) * NCOLS + p]),
            h2u(U[(k0 + 24) * NCOLS + p], U[(k0 + 25) * NCOLS + p]));
    }
    if (idx < 2 * NCOLS * 4) {
        int q   = idx & 3;
        int Lp  = (idx >> 2) & (NCOLS - 1);
        int ko4 = idx >> 12;
        int p   = phys_col(Lp);
        int k0  = ko4 * 32 + 2 * q;
        #define WV(kk) (((kk) < F_IN) ? W[(kk) * NCOLS + p] : 0.0f)
        g_Wp[idx] = make_uint4(
            h2u(WV(k0),      WV(k0 +  1)),
            h2u(WV(k0 +  8), WV(k0 +  9)),
            h2u(WV(k0 + 16), WV(k0 + 17)),
            h2u(WV(k0 + 24), WV(k0 + 25)));
        #undef WV
    }
    if (idx < NCOLS) {
        g_bp[idx] = b[phys_col(idx)];
    }
}

__device__ __forceinline__ void mma16(float (&c)[4], const unsigned (&a)[4],
                                      unsigned b0, unsigned b1) {
    asm volatile(
        "mma.sync.aligned.m16n8k16.row.col.f32.f16.f16.f32 "
        "{%0,%1,%2,%3}, {%4,%5,%6,%7}, {%8,%9}, {%0,%1,%2,%3};\n"
        : "+f"(c[0]), "+f"(c[1]), "+f"(c[2]), "+f"(c[3])
        : "r"(a[0]), "r"(a[1]), "r"(a[2]), "r"(a[3]), "r"(b0), "r"(b1));
}

__device__ __forceinline__ float sigmoidf_(float x) {
    return __fdividef(1.0f, 1.0f + __expf(-x));
}
__device__ __forceinline__ float tanhf_(float x) {
    return 1.0f - __fdividef(2.0f, __expf(2.0f * x) + 1.0f);
}

// VERBATIM round-12 gemm16 (M=32 band)
template <int KOT4>
__device__ __forceinline__ void gemm16(
    float (&acc)[2][2][2][4], const __half* __restrict__ As, int aStride,
    const uint4* __restrict__ Bp, int idxBase, int lane)
{
    const int q  = lane & 3;
    const int rA = lane >> 2;

    uint4 bbuf[2][2][2];
    #pragma unroll
    for (int p = 0; p < 2 && p < KOT4; ++p)
        #pragma unroll
        for (int cp = 0; cp < 2; ++cp)
            #pragma unroll
            for (int nt = 0; nt < 2; ++nt)
                bbuf[p][cp][nt] = Bp[idxBase + p * 4096 + cp * 512 + nt * 32];

    #pragma unroll
    for (int ko4 = 0; ko4 < KOT4; ++ko4) {
        const int p = ko4 & 1;

        unsigned a[2][2][4];   // [blk][mt][frag]
        #pragma unroll
        for (int mt = 0; mt < 2; ++mt) {
            const __half* ap = As + (rA + mt * 16) * aStride + ko4 * 32 + q * 8;
            uint4 lo = *reinterpret_cast<const uint4*>(ap);
            uint4 hi = *reinterpret_cast<const uint4*>(ap + 8 * aStride);
            a[0][mt][0] = lo.x; a[0][mt][1] = hi.x; a[0][mt][2] = lo.y; a[0][mt][3] = hi.y;
            a[1][mt][0] = lo.z; a[1][mt][1] = hi.z; a[1][mt][2] = lo.w; a[1][mt][3] = hi.w;
        }

        #pragma unroll
        for (int cp = 0; cp < 2; ++cp) {
            #pragma unroll
            for (int nt = 0; nt < 2; ++nt) {
                uint4 b = bbuf[p][cp][nt];
                mma16(acc[0][cp][nt], a[0][0], b.x, b.y);
                mma16(acc[1][cp][nt], a[0][1], b.x, b.y);
                mma16(acc[0][cp][nt], a[1][0], b.z, b.w);
                mma16(acc[1][cp][nt], a[1][1], b.z, b.w);
            }
        }

        if (ko4 + 2 < KOT4) {
            #pragma unroll
            for (int cp = 0; cp < 2; ++cp)
                #pragma unroll
                for (int nt = 0; nt < 2; ++nt)
                    bbuf[p][cp][nt] = Bp[idxBase + (ko4 + 2) * 4096 + cp * 512 + nt * 32];
        }
    }
}

__global__ void __launch_bounds__(NTHREADS, 2)
lstm_enc_kernel(const float* __restrict__ xg, float* __restrict__ out)
{
    extern __shared__ char smemc[];
    float*  cs = reinterpret_cast<float*>(smemc);                               // [BM][SC]
    __half* xs = reinterpret_cast<__half*>(smemc + BM * SC * 4);                // [BM][SXH]
    __half* hs = reinterpret_cast<__half*>(smemc + BM * SC * 4 + BM * SXH * 2); // [2][BM][SHH]

    const int tid  = threadIdx.x;
    const int lane = tid & 31;
    const int wn   = tid >> 5;        // 0..7 (same role as round 9)
    const int q    = lane & 3;
    const int rA   = lane >> 2;
    const int row0 = blockIdx.x * BM;

    for (int idx = tid; idx < BM * SC; idx += NTHREADS) cs[idx] = 0.0f;

    for (int t = 0; t < T_STEPS; ++t) {
        __syncthreads();

        // stage x_t as fp16 packed; zero-pad k=60..63 (VERBATIM round-12 form)
        for (int idx = tid; idx < BM * F_IN; idx += NTHREADS) {
            int row = idx / F_IN;
            int col = idx - row * F_IN;
            float v = xg[(size_t)(row0 + row) * (T_STEPS * F_IN) + t * F_IN + col];
            xs[row * SXH + kpos(col)] = __float2half_rn(v);
        }
        for (int idx = tid; idx < BM * 4; idx += NTHREADS) {
            int row = idx >> 2;
            xs[row * SXH + kpos(60 + (idx & 3))] = __ushort_as_half(0);
        }
        __syncthreads();

        const int rb = t & 1;
        const __half* hrd = hs + rb * (BM * SHH);
        __half*       hwr = hs + (rb ^ 1) * (BM * SHH);

        // each warp runs all 4 ch2 passes -> every B slice loaded exactly once per CTA
        for (int ch2 = 0; ch2 < 4; ++ch2) {
            const int idxBase = ((ch2 * 256 + wn * 16 + rA) << 2) + q;

            float acc[2][2][2][4];
            const float2* bp2 = reinterpret_cast<const float2*>(g_bp);
            #pragma unroll
            for (int cp = 0; cp < 2; ++cp) {
                const int ch = ch2 * 2 + cp;
                #pragma unroll
                for (int nt = 0; nt < 2; ++nt) {
                    float2 bb = bp2[ch * 64 + wn * 8 + nt * 4 + q];
                    acc[0][cp][nt][0] = bb.x; acc[0][cp][nt][1] = bb.y;
                    acc[0][cp][nt][2] = bb.x; acc[0][cp][nt][3] = bb.y;
                    acc[1][cp][nt][0] = bb.x; acc[1][cp][nt][1] = bb.y;
                    acc[1][cp][nt][2] = bb.x; acc[1][cp][nt][3] = bb.y;
                }
            }

            gemm16<2>(acc, xs, SXH, g_Wp, idxBase, lane);
            if (t > 0)
                gemm16<8>(acc, hrd, SHH, g_Up, idxBase, lane);

            // epilogue (VERBATIM formulas)
            #pragma unroll
            for (int cp = 0; cp < 2; ++cp) {
                const int unit = (ch2 * 2 + cp) * 32 + wn * 4 + q;
                const int kp   = kpos(unit);
                #pragma unroll
                for (int mt = 0; mt < 2; ++mt) {
                    const int rowL = mt * 16 + rA;
                    float zi0 = acc[mt][cp][0][0], zf0 = acc[mt][cp][0][1];
                    float zi1 = acc[mt][cp][0][2], zf1 = acc[mt][cp][0][3];
                    float zg0 = acc[mt][cp][1][0], zo0 = acc[mt][cp][1][1];
                    float zg1 = acc[mt][cp][1][2], zo1 = acc[mt][cp][1][3];

                    float c0 = cs[rowL * SC + unit];
                    float c1 = cs[(rowL + 8) * SC + unit];
                    float cn0 = sigmoidf_(zf0) * c0 + sigmoidf_(zi0) * tanhf_(zg0);
                    float cn1 = sigmoidf_(zf1) * c1 + sigmoidf_(zi1) * tanhf_(zg1);
                    cs[rowL * SC + unit]       = cn0;
                    cs[(rowL + 8) * SC + unit] = cn1;
                    float h0 = sigmoidf_(zo0) * tanhf_(cn0);
                    float h1 = sigmoidf_(zo1) * tanhf_(cn1);

                    hwr[rowL * SHH + kp]       = __float2half_rn(h0);
                    hwr[(rowL + 8) * SHH + kp] = __float2half_rn(h1);

                    if (t == T_STEPS - 1) {
                        size_t g0i = (size_t)(row0 + rowL) * UNITS + unit;
                        size_t g1i = (size_t)(row0 + rowL + 8) * UNITS + unit;
                        const size_t HOFF = (size_t)B_TOTAL * UNITS;
                        const size_t COFF = 2 * HOFF;
                        out[g0i] = h0;          out[g1i] = h1;
                        out[HOFF + g0i] = h0;   out[HOFF + g1i] = h1;
                        out[COFF + g0i] = cn0;  out[COFF + g1i] = cn1;
                    }
                }
            }
        }
    }
}

extern "C" void kernel_launch(void* const* d_in, const int* in_sizes, int n_in,
                              void* d_out, int out_size) {
    const float* x = nullptr;
    const float* W = nullptr;
    const float* U = nullptr;
    const float* b = nullptr;
    for (int i = 0; i < n_in; ++i) {
        switch (in_sizes[i]) {
            case B_TOTAL * T_STEPS * F_IN: x = (const float*)d_in[i]; break;
            case F_IN * NCOLS:             W = (const float*)d_in[i]; break;
            case UNITS * NCOLS:            U = (const float*)d_in[i]; break;
            case NCOLS:                    b = (const float*)d_in[i]; break;
            default: break;
        }
    }
    if (!x) x = (const float*)d_in[0];
    if (!W) W = (const float*)d_in[1];
    if (!U) U = (const float*)d_in[2];
    if (!b) b = (const float*)d_in[3];

    float* out = (float*)d_out;

    pack_kernel<<<128, 256>>>(W, U, b);

    // smem: c fp32 [32][260] + x fp16 [32][96] + h fp16 [2][32][288] = 76288 B (x2 CTAs/SM)
    const int smem_bytes = BM * SC * 4 + BM * SXH * 2 + 2 * BM * SHH * 2;
    cudaFuncSetAttribute(lstm_enc_kernel,
                         cudaFuncAttributeMaxDynamicSharedMemorySize, smem_bytes);
    lstm_enc_kernel<<<B_TOTAL / BM, NTHREADS, smem_bytes>>>(x, out);
}